// round 9
// baseline (speedup 1.0000x reference)
#include <cuda_runtime.h>
#include <cuda_bf16.h>
#include <math.h>
#include <stdint.h>

#define D 128
#define N_MAX 50048
#define TILE_N 256
#define MLP_THREADS 512
#define SAW 68   // smem row stride in 32-bit words (ldmatrix conflict-free)

// Scratch (device globals — no allocation allowed)
__device__ float g_deg[N_MAX];
__device__ float g_norm[N_MAX];
__device__ float g_agg[(size_t)N_MAX * D];

// ---------------------------------------------------------------------------
// bf16x2 / mma / ldmatrix helpers
// ---------------------------------------------------------------------------
__device__ __forceinline__ uint32_t pack_bf16x2(float v_lo, float v_hi) {
    uint32_t r;
    asm("cvt.rn.bf16x2.f32 %0, %1, %2;" : "=r"(r) : "f"(v_hi), "f"(v_lo));
    return r;
}
__device__ __forceinline__ void split2(float v0, float v1,
                                       uint32_t& hi, uint32_t& lo) {
    hi = pack_bf16x2(v0, v1);
    float h0 = __uint_as_float(hi << 16);
    float h1 = __uint_as_float(hi & 0xffff0000u);
    lo = pack_bf16x2(v0 - h0, v1 - h1);
}
__device__ __forceinline__ void mma_bf16(float d[4],
                                         uint32_t a0, uint32_t a1,
                                         uint32_t a2, uint32_t a3,
                                         uint32_t b0, uint32_t b1) {
    asm volatile(
        "mma.sync.aligned.m16n8k16.row.col.f32.bf16.bf16.f32 "
        "{%0,%1,%2,%3}, {%4,%5,%6,%7}, {%8,%9}, {%0,%1,%2,%3};"
        : "+f"(d[0]), "+f"(d[1]), "+f"(d[2]), "+f"(d[3])
        : "r"(a0), "r"(a1), "r"(a2), "r"(a3), "r"(b0), "r"(b1));
}
#define LDSM4(r0, r1, r2, r3, addr)                                         \
    asm volatile("ldmatrix.sync.aligned.m8n8.x4.shared.b16 "                \
                 "{%0,%1,%2,%3}, [%4];"                                     \
                 : "=r"(r0), "=r"(r1), "=r"(r2), "=r"(r3) : "r"(addr))

// ---------------------------------------------------------------------------
// 1) in-degree count over dst
// ---------------------------------------------------------------------------
__global__ void deg_kernel(const int* __restrict__ dst, int E) {
    int i = blockIdx.x * blockDim.x + threadIdx.x;
    if (i < E) atomicAdd(&g_deg[dst[i]], 1.0f);
}

// ---------------------------------------------------------------------------
// 2) norm = rsqrt(max(deg,1))
// ---------------------------------------------------------------------------
__global__ void norm_kernel(int N) {
    int i = blockIdx.x * blockDim.x + threadIdx.x;
    if (i < N) g_norm[i] = rsqrtf(fmaxf(g_deg[i], 1.0f));
}

// ---------------------------------------------------------------------------
// 3) SPMM: agg[dst] += x[src] * norm[src]  (one warp per edge, red.v4 scatter)
// ---------------------------------------------------------------------------
__global__ void spmm_kernel(const float* __restrict__ x,
                            const int* __restrict__ src,
                            const int* __restrict__ dst,
                            int E) {
    int t = blockIdx.x * blockDim.x + threadIdx.x;
    int e = t >> 5;
    int lane = t & 31;
    if (e >= E) return;
    int s = __ldg(&src[e]);
    int d = __ldg(&dst[e]);
    float ns = __ldg((const float*)&g_norm[s]);
    float4 v = __ldg(((const float4*)(x + (size_t)s * D)) + lane);
    v.x *= ns; v.y *= ns; v.z *= ns; v.w *= ns;
    float* p = &g_agg[(size_t)d * D + lane * 4];
    asm volatile("red.global.add.v4.f32 [%0], {%1, %2, %3, %4};"
                 :: "l"(p), "f"(v.x), "f"(v.y), "f"(v.z), "f"(v.w)
                 : "memory");
}

// ---------------------------------------------------------------------------
// bf16-split GEMM mainloop via ldmatrix: pure LDSM + HMMA.
//   a_hi/a_lo/w_hi/w_lo are shared-space byte addresses pre-offset with the
//   warp tile origin and the per-lane ldmatrix pattern.
// ---------------------------------------------------------------------------
__device__ __forceinline__ void gemm_ldsm(uint32_t a_hi, uint32_t a_lo,
                                          uint32_t w_hi, uint32_t w_lo,
                                          float d[4][4][4]) {
    #pragma unroll
    for (int kb = 0; kb < 64; kb += 8) {    // 8 kpairs = k16 per step
        uint32_t bh[4][2], bl[4][2];
        LDSM4(bh[0][0], bh[0][1], bh[1][0], bh[1][1], w_hi + 4 * kb);
        LDSM4(bh[2][0], bh[2][1], bh[3][0], bh[3][1], w_hi + 4 * (16 * SAW + kb));
        LDSM4(bl[0][0], bl[0][1], bl[1][0], bl[1][1], w_lo + 4 * kb);
        LDSM4(bl[2][0], bl[2][1], bl[3][0], bl[3][1], w_lo + 4 * (16 * SAW + kb));
        #pragma unroll
        for (int mi = 0; mi < 4; mi++) {
            uint32_t ah0, ah1, ah2, ah3, al0, al1, al2, al3;
            LDSM4(ah0, ah1, ah2, ah3, a_hi + 4 * (mi * 16 * SAW + kb));
            LDSM4(al0, al1, al2, al3, a_lo + 4 * (mi * 16 * SAW + kb));
            #pragma unroll
            for (int ni = 0; ni < 4; ni++) {
                mma_bf16(d[mi][ni], ah0, ah1, ah2, ah3, bh[ni][0], bh[ni][1]);
                mma_bf16(d[mi][ni], ah0, ah1, ah2, ah3, bl[ni][0], bl[ni][1]);
                mma_bf16(d[mi][ni], al0, al1, al2, al3, bh[ni][0], bh[ni][1]);
            }
        }
    }
}

// ---------------------------------------------------------------------------
// 4) Fused 2-layer MLP on tensor cores (bf16 2-way split, 3 terms, LDSM).
//    512 threads; warp grid 4(m) x 4(n); tile 256 nodes x 128 outs.
// ---------------------------------------------------------------------------
__global__ void __launch_bounds__(MLP_THREADS, 1)
mlp_kernel(const float* __restrict__ wc, const float* __restrict__ bc,
           const float* __restrict__ wl, const float* __restrict__ bl,
           float* __restrict__ out, int N) {
    extern __shared__ uint32_t sm[];
    uint32_t* s_ahi = sm;                      // [256][SAW]
    uint32_t* s_alo = s_ahi + 256 * SAW;       // [256][SAW]
    uint32_t* s_whi = s_alo + 256 * SAW;       // [128][SAW]
    uint32_t* s_wlo = s_whi + 128 * SAW;       // [128][SAW]

    const int tid = threadIdx.x;
    const int lane = tid & 31;
    const int wid = tid >> 5;
    const int warp_m = wid >> 2;   // 0..3
    const int warp_n = wid & 3;    // 0..3
    const int g = lane >> 2;       // 0..7
    const int q = lane & 3;        // 0..3
    const int n0 = blockIdx.x * TILE_N;

    uint32_t sbase;
    asm("{ .reg .u64 t; cvta.to.shared.u64 t, %1; cvt.u32.u64 %0, t; }"
        : "=r"(sbase) : "l"(sm));

    // ldmatrix per-lane patterns (in words)
    const int a_lane = ((lane & 7) + ((lane >> 3) & 1) * 8) * SAW + (lane >> 4) * 4;
    const int b_lane = ((lane >> 4) * 8 + (lane & 7)) * SAW + ((lane >> 3) & 1) * 4;

    const uint32_t a_hi = sbase + 4 * ((warp_m * 64) * SAW + a_lane);
    const uint32_t a_lo = a_hi + 4 * (256 * SAW);
    const uint32_t w_hi = sbase + 4 * (512 * SAW + (warp_n * 32) * SAW + b_lane);
    const uint32_t w_lo = w_hi + 4 * (128 * SAW);

    // ---- fill w1: [o][kpair], split hi/lo ----
    for (int i = tid; i < 128 * 64; i += MLP_THREADS) {
        int o = i >> 6, kp = i & 63;
        float2 w = *(const float2*)&wc[o * 128 + kp * 2];
        uint32_t hi, lo;
        split2(w.x, w.y, hi, lo);
        s_whi[o * SAW + kp] = hi;
        s_wlo[o * SAW + kp] = lo;
    }
    // ---- fill input tile: agg[n][k] * norm[n], split hi/lo ----
    for (int i = tid; i < TILE_N * 64; i += MLP_THREADS) {
        int n = i >> 6, kp = i & 63;
        int gn = n0 + n;
        float2 v = make_float2(0.f, 0.f);
        float nn = 0.f;
        if (gn < N) {
            v = *(const float2*)&g_agg[(size_t)gn * 128 + kp * 2];
            nn = g_norm[gn];
        }
        uint32_t hi, lo;
        split2(v.x * nn, v.y * nn, hi, lo);
        s_ahi[n * SAW + kp] = hi;
        s_alo[n * SAW + kp] = lo;
    }
    __syncthreads();

    float d[4][4][4];

    // ================= GEMM 1 =================
    #pragma unroll
    for (int mi = 0; mi < 4; mi++)
        #pragma unroll
        for (int ni = 0; ni < 4; ni++)
            #pragma unroll
            for (int p = 0; p < 4; p++) d[mi][ni][p] = 0.0f;

    gemm_ldsm(a_hi, a_lo, w_hi, w_lo, d);

    __syncthreads();   // everyone done reading s_a / s_w

    // ---- epilogue 1: h = relu(d + bc), split & write back to s_a ----
    {
        #pragma unroll
        for (int ni = 0; ni < 4; ni++) {
            int col = warp_n * 32 + ni * 8 + q * 2;
            int kp = col >> 1;
            float2 b = *(const float2*)&bc[col];
            #pragma unroll
            for (int mi = 0; mi < 4; mi++) {
                int row = warp_m * 64 + mi * 16 + g;
                float h0 = fmaxf(d[mi][ni][0] + b.x, 0.0f);
                float h1 = fmaxf(d[mi][ni][1] + b.y, 0.0f);
                float h2 = fmaxf(d[mi][ni][2] + b.x, 0.0f);
                float h3 = fmaxf(d[mi][ni][3] + b.y, 0.0f);
                uint32_t hi, lo;
                split2(h0, h1, hi, lo);
                s_ahi[row * SAW + kp] = hi;
                s_alo[row * SAW + kp] = lo;
                split2(h2, h3, hi, lo);
                s_ahi[(row + 8) * SAW + kp] = hi;
                s_alo[(row + 8) * SAW + kp] = lo;
            }
        }
    }
    // ---- fill w2 split hi/lo ----
    for (int i = tid; i < 128 * 64; i += MLP_THREADS) {
        int o = i >> 6, kp = i & 63;
        float2 w = *(const float2*)&wl[o * 128 + kp * 2];
        uint32_t hi, lo;
        split2(w.x, w.y, hi, lo);
        s_whi[o * SAW + kp] = hi;
        s_wlo[o * SAW + kp] = lo;
    }
    __syncthreads();

    // ================= GEMM 2 =================
    #pragma unroll
    for (int mi = 0; mi < 4; mi++)
        #pragma unroll
        for (int ni = 0; ni < 4; ni++)
            #pragma unroll
            for (int p = 0; p < 4; p++) d[mi][ni][p] = 0.0f;

    gemm_ldsm(a_hi, a_lo, w_hi, w_lo, d);

    // ---- epilogue 2: out = relu(d + bl) -> gmem ----
    {
        #pragma unroll
        for (int ni = 0; ni < 4; ni++) {
            int col = warp_n * 32 + ni * 8 + q * 2;
            float2 b = *(const float2*)&bl[col];
            #pragma unroll
            for (int mi = 0; mi < 4; mi++) {
                int row = warp_m * 64 + mi * 16 + g;
                int gn0 = n0 + row;
                int gn1 = gn0 + 8;
                if (gn0 < N) {
                    float2 v = make_float2(fmaxf(d[mi][ni][0] + b.x, 0.0f),
                                           fmaxf(d[mi][ni][1] + b.y, 0.0f));
                    *(float2*)&out[(size_t)gn0 * 128 + col] = v;
                }
                if (gn1 < N) {
                    float2 v = make_float2(fmaxf(d[mi][ni][2] + b.x, 0.0f),
                                           fmaxf(d[mi][ni][3] + b.y, 0.0f));
                    *(float2*)&out[(size_t)gn1 * 128 + col] = v;
                }
            }
        }
    }
}

// ---------------------------------------------------------------------------
extern "C" void kernel_launch(void* const* d_in, const int* in_sizes, int n_in,
                              void* d_out, int out_size) {
    const float* x    = (const float*)d_in[0];
    const int*   src  = (const int*)  d_in[1];
    const int*   dst  = (const int*)  d_in[2];
    const float* wc   = (const float*)d_in[3];
    const float* bc   = (const float*)d_in[4];
    const float* wl   = (const float*)d_in[5];
    const float* bl   = (const float*)d_in[6];
    float* out = (float*)d_out;

    const int N = in_sizes[0] / D;
    const int E = in_sizes[1];

    void* p_deg = nullptr;
    void* p_agg = nullptr;
    cudaGetSymbolAddress(&p_deg, g_deg);
    cudaGetSymbolAddress(&p_agg, g_agg);
    cudaMemsetAsync(p_deg, 0, (size_t)N * sizeof(float));
    cudaMemsetAsync(p_agg, 0, (size_t)N * D * sizeof(float));

    deg_kernel<<<(E + 255) / 256, 256>>>(dst, E);
    norm_kernel<<<(N + 255) / 256, 256>>>(N);

    long long spmm_threads = (long long)E * 32;
    int spmm_blocks = (int)((spmm_threads + 255) / 256);
    spmm_kernel<<<spmm_blocks, 256>>>(x, src, dst, E);

    const int smem_bytes = 768 * SAW * sizeof(uint32_t);  // ~204KB
    cudaFuncSetAttribute(mlp_kernel, cudaFuncAttributeMaxDynamicSharedMemorySize, smem_bytes);
    int mlp_blocks = (N + TILE_N - 1) / TILE_N;
    mlp_kernel<<<mlp_blocks, MLP_THREADS, smem_bytes>>>(wc, bc, wl, bl, out, N);
}

// round 10
// speedup vs baseline: 1.0402x; 1.0402x over previous
#include <cuda_runtime.h>
#include <cuda_bf16.h>
#include <math.h>
#include <stdint.h>

#define D 128
#define N_MAX 50048
#define TILE_N 128
#define MLP_THREADS 256
#define SAW 68   // smem row stride in 32-bit words (ldmatrix conflict-free)

// Scratch (device globals — no allocation allowed)
__device__ float g_deg[N_MAX];
__device__ float g_norm[N_MAX];
__device__ float g_agg[(size_t)N_MAX * D];

// ---------------------------------------------------------------------------
// bf16x2 / mma / ldmatrix helpers
// ---------------------------------------------------------------------------
__device__ __forceinline__ uint32_t pack_bf16x2(float v_lo, float v_hi) {
    uint32_t r;
    asm("cvt.rn.bf16x2.f32 %0, %1, %2;" : "=r"(r) : "f"(v_hi), "f"(v_lo));
    return r;
}
__device__ __forceinline__ void split2(float v0, float v1,
                                       uint32_t& hi, uint32_t& lo) {
    hi = pack_bf16x2(v0, v1);
    float h0 = __uint_as_float(hi << 16);
    float h1 = __uint_as_float(hi & 0xffff0000u);
    lo = pack_bf16x2(v0 - h0, v1 - h1);
}
__device__ __forceinline__ void mma_bf16(float d[4],
                                         uint32_t a0, uint32_t a1,
                                         uint32_t a2, uint32_t a3,
                                         uint32_t b0, uint32_t b1) {
    asm volatile(
        "mma.sync.aligned.m16n8k16.row.col.f32.bf16.bf16.f32 "
        "{%0,%1,%2,%3}, {%4,%5,%6,%7}, {%8,%9}, {%0,%1,%2,%3};"
        : "+f"(d[0]), "+f"(d[1]), "+f"(d[2]), "+f"(d[3])
        : "r"(a0), "r"(a1), "r"(a2), "r"(a3), "r"(b0), "r"(b1));
}
#define LDSM4(r0, r1, r2, r3, addr)                                         \
    asm volatile("ldmatrix.sync.aligned.m8n8.x4.shared.b16 "                \
                 "{%0,%1,%2,%3}, [%4];"                                     \
                 : "=r"(r0), "=r"(r1), "=r"(r2), "=r"(r3) : "r"(addr))

// ---------------------------------------------------------------------------
// 1) in-degree count over dst
// ---------------------------------------------------------------------------
__global__ void deg_kernel(const int* __restrict__ dst, int E) {
    int i = blockIdx.x * blockDim.x + threadIdx.x;
    if (i < E) atomicAdd(&g_deg[dst[i]], 1.0f);
}

// ---------------------------------------------------------------------------
// 2) norm = rsqrt(max(deg,1))
// ---------------------------------------------------------------------------
__global__ void norm_kernel(int N) {
    int i = blockIdx.x * blockDim.x + threadIdx.x;
    if (i < N) g_norm[i] = rsqrtf(fmaxf(g_deg[i], 1.0f));
}

// ---------------------------------------------------------------------------
// 3) SPMM: agg[dst] += x[src] * norm[src]  (one warp per edge, red.v4 scatter)
// ---------------------------------------------------------------------------
__global__ void spmm_kernel(const float* __restrict__ x,
                            const int* __restrict__ src,
                            const int* __restrict__ dst,
                            int E) {
    int t = blockIdx.x * blockDim.x + threadIdx.x;
    int e = t >> 5;
    int lane = t & 31;
    if (e >= E) return;
    int s = __ldg(&src[e]);
    int d = __ldg(&dst[e]);
    float ns = __ldg((const float*)&g_norm[s]);
    float4 v = __ldg(((const float4*)(x + (size_t)s * D)) + lane);
    v.x *= ns; v.y *= ns; v.z *= ns; v.w *= ns;
    float* p = &g_agg[(size_t)d * D + lane * 4];
    asm volatile("red.global.add.v4.f32 [%0], {%1, %2, %3, %4};"
                 :: "l"(p), "f"(v.x), "f"(v.y), "f"(v.z), "f"(v.w)
                 : "memory");
}

// ---------------------------------------------------------------------------
// bf16-split GEMM mainloop via ldmatrix: pure LDSM + HMMA.
// ---------------------------------------------------------------------------
__device__ __forceinline__ void gemm_ldsm(uint32_t a_hi, uint32_t a_lo,
                                          uint32_t w_hi, uint32_t w_lo,
                                          float d[4][4][4]) {
    #pragma unroll
    for (int kb = 0; kb < 64; kb += 8) {    // 8 kpairs = k16 per step
        uint32_t bh[4][2], bl[4][2];
        LDSM4(bh[0][0], bh[0][1], bh[1][0], bh[1][1], w_hi + 4 * kb);
        LDSM4(bh[2][0], bh[2][1], bh[3][0], bh[3][1], w_hi + 4 * (16 * SAW + kb));
        LDSM4(bl[0][0], bl[0][1], bl[1][0], bl[1][1], w_lo + 4 * kb);
        LDSM4(bl[2][0], bl[2][1], bl[3][0], bl[3][1], w_lo + 4 * (16 * SAW + kb));
        #pragma unroll
        for (int mi = 0; mi < 4; mi++) {
            uint32_t ah0, ah1, ah2, ah3, al0, al1, al2, al3;
            LDSM4(ah0, ah1, ah2, ah3, a_hi + 4 * (mi * 16 * SAW + kb));
            LDSM4(al0, al1, al2, al3, a_lo + 4 * (mi * 16 * SAW + kb));
            #pragma unroll
            for (int ni = 0; ni < 4; ni++) {
                mma_bf16(d[mi][ni], ah0, ah1, ah2, ah3, bh[ni][0], bh[ni][1]);
                mma_bf16(d[mi][ni], ah0, ah1, ah2, ah3, bl[ni][0], bl[ni][1]);
                mma_bf16(d[mi][ni], al0, al1, al2, al3, bh[ni][0], bh[ni][1]);
            }
        }
    }
}

// ---------------------------------------------------------------------------
// 4) Fused 2-layer MLP on tensor cores (bf16 2-way split, 3 terms, LDSM).
//    256 threads; warp grid 2(m) x 4(n); tile 128 nodes x 128 outs.
// ---------------------------------------------------------------------------
__global__ void __launch_bounds__(MLP_THREADS, 1)
mlp_kernel(const float* __restrict__ wc, const float* __restrict__ bc,
           const float* __restrict__ wl, const float* __restrict__ bl,
           float* __restrict__ out, int N) {
    extern __shared__ uint32_t sm[];
    uint32_t* s_ahi = sm;                      // [128][SAW]
    uint32_t* s_alo = s_ahi + 128 * SAW;       // [128][SAW]
    uint32_t* s_whi = s_alo + 128 * SAW;       // [128][SAW]
    uint32_t* s_wlo = s_whi + 128 * SAW;       // [128][SAW]

    const int tid = threadIdx.x;
    const int lane = tid & 31;
    const int wid = tid >> 5;
    const int warp_m = wid >> 2;   // 0..1
    const int warp_n = wid & 3;    // 0..3
    const int g = lane >> 2;       // 0..7
    const int q = lane & 3;        // 0..3
    const int n0 = blockIdx.x * TILE_N;

    uint32_t sbase;
    asm("{ .reg .u64 t; cvta.to.shared.u64 t, %1; cvt.u32.u64 %0, t; }"
        : "=r"(sbase) : "l"(sm));

    // ldmatrix per-lane patterns (in words)
    const int a_lane = (lane & 15) * SAW + (lane >> 4) * 4;
    const int b_lane = ((lane >> 4) * 8 + (lane & 7)) * SAW + ((lane >> 3) & 1) * 4;

    const uint32_t a_hi = sbase + 4 * ((warp_m * 64) * SAW + a_lane);
    const uint32_t a_lo = a_hi + 4 * (128 * SAW);
    const uint32_t w_hi = sbase + 4 * (256 * SAW + (warp_n * 32) * SAW + b_lane);
    const uint32_t w_lo = w_hi + 4 * (128 * SAW);

    // ---- fill w1: [o][kpair], split hi/lo ----
    for (int i = tid; i < 128 * 64; i += MLP_THREADS) {
        int o = i >> 6, kp = i & 63;
        float2 w = *(const float2*)&wc[o * 128 + kp * 2];
        uint32_t hi, lo;
        split2(w.x, w.y, hi, lo);
        s_whi[o * SAW + kp] = hi;
        s_wlo[o * SAW + kp] = lo;
    }
    // ---- fill input tile: agg[n][k] * norm[n], split hi/lo ----
    for (int i = tid; i < TILE_N * 64; i += MLP_THREADS) {
        int n = i >> 6, kp = i & 63;
        int gn = n0 + n;
        float2 v = make_float2(0.f, 0.f);
        float nn = 0.f;
        if (gn < N) {
            v = *(const float2*)&g_agg[(size_t)gn * 128 + kp * 2];
            nn = g_norm[gn];
        }
        uint32_t hi, lo;
        split2(v.x * nn, v.y * nn, hi, lo);
        s_ahi[n * SAW + kp] = hi;
        s_alo[n * SAW + kp] = lo;
    }
    __syncthreads();

    float d[4][4][4];

    // ================= GEMM 1 =================
    #pragma unroll
    for (int mi = 0; mi < 4; mi++)
        #pragma unroll
        for (int ni = 0; ni < 4; ni++)
            #pragma unroll
            for (int p = 0; p < 4; p++) d[mi][ni][p] = 0.0f;

    gemm_ldsm(a_hi, a_lo, w_hi, w_lo, d);

    __syncthreads();   // everyone done reading s_a / s_w

    // ---- epilogue 1: h = relu(d + bc), split & write back to s_a ----
    {
        #pragma unroll
        for (int ni = 0; ni < 4; ni++) {
            int col = warp_n * 32 + ni * 8 + q * 2;
            int kp = col >> 1;
            float2 b = *(const float2*)&bc[col];
            #pragma unroll
            for (int mi = 0; mi < 4; mi++) {
                int row = warp_m * 64 + mi * 16 + g;
                float h0 = fmaxf(d[mi][ni][0] + b.x, 0.0f);
                float h1 = fmaxf(d[mi][ni][1] + b.y, 0.0f);
                float h2 = fmaxf(d[mi][ni][2] + b.x, 0.0f);
                float h3 = fmaxf(d[mi][ni][3] + b.y, 0.0f);
                uint32_t hi, lo;
                split2(h0, h1, hi, lo);
                s_ahi[row * SAW + kp] = hi;
                s_alo[row * SAW + kp] = lo;
                split2(h2, h3, hi, lo);
                s_ahi[(row + 8) * SAW + kp] = hi;
                s_alo[(row + 8) * SAW + kp] = lo;
            }
        }
    }
    // ---- fill w2 split hi/lo ----
    for (int i = tid; i < 128 * 64; i += MLP_THREADS) {
        int o = i >> 6, kp = i & 63;
        float2 w = *(const float2*)&wl[o * 128 + kp * 2];
        uint32_t hi, lo;
        split2(w.x, w.y, hi, lo);
        s_whi[o * SAW + kp] = hi;
        s_wlo[o * SAW + kp] = lo;
    }
    __syncthreads();

    // ================= GEMM 2 =================
    #pragma unroll
    for (int mi = 0; mi < 4; mi++)
        #pragma unroll
        for (int ni = 0; ni < 4; ni++)
            #pragma unroll
            for (int p = 0; p < 4; p++) d[mi][ni][p] = 0.0f;

    gemm_ldsm(a_hi, a_lo, w_hi, w_lo, d);

    // ---- epilogue 2: out = relu(d + bl) -> gmem ----
    {
        #pragma unroll
        for (int ni = 0; ni < 4; ni++) {
            int col = warp_n * 32 + ni * 8 + q * 2;
            float2 b = *(const float2*)&bl[col];
            #pragma unroll
            for (int mi = 0; mi < 4; mi++) {
                int row = warp_m * 64 + mi * 16 + g;
                int gn0 = n0 + row;
                int gn1 = gn0 + 8;
                if (gn0 < N) {
                    float2 v = make_float2(fmaxf(d[mi][ni][0] + b.x, 0.0f),
                                           fmaxf(d[mi][ni][1] + b.y, 0.0f));
                    *(float2*)&out[(size_t)gn0 * 128 + col] = v;
                }
                if (gn1 < N) {
                    float2 v = make_float2(fmaxf(d[mi][ni][2] + b.x, 0.0f),
                                           fmaxf(d[mi][ni][3] + b.y, 0.0f));
                    *(float2*)&out[(size_t)gn1 * 128 + col] = v;
                }
            }
        }
    }
}

// ---------------------------------------------------------------------------
extern "C" void kernel_launch(void* const* d_in, const int* in_sizes, int n_in,
                              void* d_out, int out_size) {
    const float* x    = (const float*)d_in[0];
    const int*   src  = (const int*)  d_in[1];
    const int*   dst  = (const int*)  d_in[2];
    const float* wc   = (const float*)d_in[3];
    const float* bc   = (const float*)d_in[4];
    const float* wl   = (const float*)d_in[5];
    const float* bl   = (const float*)d_in[6];
    float* out = (float*)d_out;

    const int N = in_sizes[0] / D;
    const int E = in_sizes[1];

    void* p_deg = nullptr;
    void* p_agg = nullptr;
    cudaGetSymbolAddress(&p_deg, g_deg);
    cudaGetSymbolAddress(&p_agg, g_agg);
    cudaMemsetAsync(p_deg, 0, (size_t)N * sizeof(float));
    cudaMemsetAsync(p_agg, 0, (size_t)N * D * sizeof(float));

    deg_kernel<<<(E + 255) / 256, 256>>>(dst, E);
    norm_kernel<<<(N + 255) / 256, 256>>>(N);

    long long spmm_threads = (long long)E * 32;
    int spmm_blocks = (int)((spmm_threads + 255) / 256);
    spmm_kernel<<<spmm_blocks, 256>>>(x, src, dst, E);

    const int smem_bytes = 512 * SAW * sizeof(uint32_t);  // ~136KB
    cudaFuncSetAttribute(mlp_kernel, cudaFuncAttributeMaxDynamicSharedMemorySize, smem_bytes);
    int mlp_blocks = (N + TILE_N - 1) / TILE_N;
    mlp_kernel<<<mlp_blocks, MLP_THREADS, smem_bytes>>>(wc, bc, wl, bl, out, N);
}